// round 4
// baseline (speedup 1.0000x reference)
#include <cuda_runtime.h>
#include <mma.h>
#include <cstddef>
#include <cstdint>

using namespace nvcuda;

#define BB 64
#define TT 512
#define DD 512
#define HH 768
#define NG 3072              // 4*H
#define MMROWS (BB * TT)     // 32768
#define NCTA 96              // 2 dirs x 48 column blocks
#define WS_LD 66             // Ws row pad (64 cols + 2)  -> (2k+n)%32 conflict-free
#define HS_LD 36             // Hs chunk row pad (32 + 4)
#define GS_LD 68
#define NSTAGE 3             // cp.async stages for h chunks

// ---------------- scratch (device globals: the sanctioned scratch path) ----
__device__ float g_xp[(size_t)2 * MMROWS * NG];   // [dir][b*T + t][4H]
__device__ float g_h[2][2][BB * HH];              // [dir][parity][b*H] (tf32-rounded)
__device__ unsigned g_bar_count;
__device__ unsigned g_bar_gen;

__device__ __forceinline__ float sigmoidf(float x) {
    return 1.0f / (1.0f + expf(-x));
}

// ---------------------------------------------------------------------------
// software grid barrier (all NCTA CTAs co-resident: 1 CTA/SM)
// ---------------------------------------------------------------------------
__device__ __forceinline__ void grid_sync() {
    __syncthreads();
    if (threadIdx.x == 0) {
        unsigned gen = *((volatile unsigned*)&g_bar_gen);
        unsigned arr = atomicAdd(&g_bar_count, 1u);
        if (arr == NCTA - 1) {
            g_bar_count = 0;
            __threadfence();
            atomicAdd(&g_bar_gen, 1u);
        } else {
            while (*((volatile unsigned*)&g_bar_gen) == gen)
                __nanosleep(32);
        }
        __threadfence();
    }
    __syncthreads();
}

// ---------------------------------------------------------------------------
// xproj: xp[dir][m, n] = seq[m, :] @ W_dir[0:D, n]   (unchanged; known-good)
// ---------------------------------------------------------------------------
__global__ void __launch_bounds__(256) xproj_kernel(
    const float* __restrict__ seq,
    const float* __restrict__ Wfw,
    const float* __restrict__ Wbw)
{
    const int dir = blockIdx.z;
    const float* W = dir ? Wbw : Wfw;
    float* xp = g_xp + (size_t)dir * MMROWS * NG;

    const int m0 = blockIdx.x * 128;
    const int n0 = blockIdx.y * 64;

    __shared__ __align__(16) float As[128][20];
    __shared__ __align__(16) float Bs[16][68];

    const int tid = threadIdx.x;
    const int w = tid >> 5;
    const int wm = w & 3;
    const int wn = w >> 2;

    wmma::fragment<wmma::accumulator, 16, 16, 8, float> acc[2][2];
#pragma unroll
    for (int i = 0; i < 2; i++)
#pragma unroll
        for (int j = 0; j < 2; j++)
            wmma::fill_fragment(acc[i][j], 0.0f);

    float ra[8], rb[4];
#pragma unroll
    for (int e = 0; e < 8; e++) {
        int idx = e * 256 + tid; int r = idx >> 4, c = idx & 15;
        ra[e] = seq[(size_t)(m0 + r) * DD + c];
    }
#pragma unroll
    for (int e = 0; e < 4; e++) {
        int idx = e * 256 + tid; int r = idx >> 6, c = idx & 63;
        rb[e] = W[(size_t)r * NG + n0 + c];
    }

    for (int kt = 0; kt < DD / 16; kt++) {
        __syncthreads();
#pragma unroll
        for (int e = 0; e < 8; e++) {
            int idx = e * 256 + tid; int r = idx >> 4, c = idx & 15;
            As[r][c] = ra[e];
        }
#pragma unroll
        for (int e = 0; e < 4; e++) {
            int idx = e * 256 + tid; int r = idx >> 6, c = idx & 63;
            Bs[r][c] = rb[e];
        }
        __syncthreads();

        if (kt + 1 < DD / 16) {
            int k0 = (kt + 1) * 16;
#pragma unroll
            for (int e = 0; e < 8; e++) {
                int idx = e * 256 + tid; int r = idx >> 4, c = idx & 15;
                ra[e] = seq[(size_t)(m0 + r) * DD + k0 + c];
            }
#pragma unroll
            for (int e = 0; e < 4; e++) {
                int idx = e * 256 + tid; int r = idx >> 6, c = idx & 63;
                rb[e] = W[(size_t)(k0 + r) * NG + n0 + c];
            }
        }

#pragma unroll
        for (int k8 = 0; k8 < 16; k8 += 8) {
            wmma::fragment<wmma::matrix_a, 16, 16, 8, wmma::precision::tf32, wmma::row_major> af[2];
            wmma::fragment<wmma::matrix_b, 16, 16, 8, wmma::precision::tf32, wmma::row_major> bf[2];
#pragma unroll
            for (int fm = 0; fm < 2; fm++) {
                wmma::load_matrix_sync(af[fm], &As[wm * 32 + fm * 16][k8], 20);
#pragma unroll
                for (int i = 0; i < af[fm].num_elements; i++)
                    af[fm].x[i] = wmma::__float_to_tf32(af[fm].x[i]);
            }
#pragma unroll
            for (int fn = 0; fn < 2; fn++) {
                wmma::load_matrix_sync(bf[fn], &Bs[k8][wn * 32 + fn * 16], 68);
#pragma unroll
                for (int i = 0; i < bf[fn].num_elements; i++)
                    bf[fn].x[i] = wmma::__float_to_tf32(bf[fn].x[i]);
            }
#pragma unroll
            for (int fm = 0; fm < 2; fm++)
#pragma unroll
                for (int fn = 0; fn < 2; fn++)
                    wmma::mma_sync(acc[fm][fn], af[fm], bf[fn], acc[fm][fn]);
        }
    }

#pragma unroll
    for (int fm = 0; fm < 2; fm++)
#pragma unroll
        for (int fn = 0; fn < 2; fn++) {
            size_t row = m0 + wm * 32 + fm * 16;
            size_t col = n0 + wn * 32 + fn * 16;
            wmma::store_matrix_sync(xp + row * NG + col, acc[fm][fn], NG,
                                    wmma::mem_row_major);
        }
}

// ---------------------------------------------------------------------------
// cp.async 16B helper (L2-only: .cg)
// ---------------------------------------------------------------------------
__device__ __forceinline__ void cp16(float* smem_dst, const float* gmem_src) {
    unsigned d = (unsigned)__cvta_generic_to_shared(smem_dst);
    asm volatile("cp.async.cg.shared.global [%0], [%1], 16;\n"
                 :: "r"(d), "l"(gmem_src));
}
__device__ __forceinline__ void cp_commit() {
    asm volatile("cp.async.commit_group;\n");
}

// ---------------------------------------------------------------------------
// Persistent recurrence kernel.
// grid = 96 CTAs (dir = bx/48, jb = bx%48 owns h-cols [jb*16, jb*16+16)).
// Per CTA: recurrent W slice (768 x 64 gate-cols, tf32) resident in smem.
// Per step: 3-stage single-sync cp.async h pipeline, 64x64x768 WMMA,
// fused cell update with c/h in registers, software grid barrier.
// h is stored tf32-rounded -> no per-use conversion in the mainloop.
// ---------------------------------------------------------------------------
__global__ void __launch_bounds__(512, 1) lstm_persistent(
    const int* __restrict__ seq_len,
    const float* __restrict__ Wfw, const float* __restrict__ bfw,
    const float* __restrict__ Wbw, const float* __restrict__ bbw,
    float* __restrict__ out)
{
    const int dir = blockIdx.x / 48;
    const int jb  = blockIdx.x % 48;
    const float* W    = dir ? Wbw : Wfw;
    const float* bias = dir ? bbw : bfw;
    const float* xp = g_xp + (size_t)dir * MMROWS * NG;

    extern __shared__ float smem[];
    float* Ws = smem;                        // [768][WS_LD]
    float* Hs = smem + 768 * WS_LD;          // [NSTAGE][64][HS_LD]
    float* Gs = Hs;                          // [64][GS_LD] overlay (post-mainloop)
    __shared__ float bs[64];

    const int tid = threadIdx.x;
    const int w  = tid >> 5;
    const int wm = w & 3;      // 16-row (batch) block
    const int wn = w >> 2;     // 16-col (gate) block

    // --- one-time: load + tf32-round recurrent weight slice ---
    for (int i = tid; i < 768 * 64; i += 512) {
        int k = i >> 6, n = i & 63;
        int g = n >> 4, c = n & 15;
        float v = W[(size_t)(DD + k) * NG + g * HH + jb * 16 + c];
        Ws[k * WS_LD + n] = wmma::__float_to_tf32(v);
    }
    if (tid < 64) {
        int g = tid >> 4, c = tid & 15;
        bs[tid] = bias[g * HH + jb * 16 + c];
    }

    // --- per-thread cell ownership: (b, j) fixed for the whole run ---
    const int j  = tid & 15;
    const int jg = jb * 16 + j;
    const int bb0 = tid >> 4;       // 0..31
    const int bb1 = bb0 + 32;       // 32..63
    const int L0 = seq_len[bb0];
    const int L1 = seq_len[bb1];
    float c0 = 0.f, c1 = 0.f, h0 = 0.f, h1 = 0.f;

    g_h[dir][0][bb0 * HH + jg] = 0.f;
    g_h[dir][0][bb1 * HH + jg] = 0.f;

    // chunk-copy thread mapping: 64 rows x 32 cols = 512 x (1 float4)
    const int cr = tid >> 3;
    const int cc = (tid & 7) * 4;
    float* hs_dst = Hs + cr * HS_LD + cc;           // + stage*64*HS_LD
    const int hsrc_off = cr * HH + cc;              // + chunk*32

    grid_sync();

    for (int t = 0; t < TT; t++) {
        const int parr = t & 1;
        const float* hsrc = g_h[dir][parr] + hsrc_off;
        float* hdst = g_h[dir][parr ^ 1];

        // xp operand prefetch (in flight across the mainloop)
        const bool a0 = t < L0, a1 = t < L1;
        const int tx0 = dir ? (a0 ? L0 - 1 - t : t) : t;
        const int tx1 = dir ? (a1 ? L1 - 1 - t : t) : t;
        const float* x0 = xp + ((size_t)bb0 * TT + tx0) * NG + jg;
        const float* x1 = xp + ((size_t)bb1 * TT + tx1) * NG + jg;
        float xv00 = x0[0], xv01 = x0[HH], xv02 = x0[2 * HH], xv03 = x0[3 * HH];
        float xv10 = x1[0], xv11 = x1[HH], xv12 = x1[2 * HH], xv13 = x1[3 * HH];

        wmma::fragment<wmma::accumulator, 16, 16, 8, float> acc;
        wmma::fill_fragment(acc, 0.f);

        // prologue: issue chunks 0, 1 (stages 0, 1)
        cp16(hs_dst + 0 * 64 * HS_LD, hsrc + 0);  cp_commit();
        cp16(hs_dst + 1 * 64 * HS_LD, hsrc + 32); cp_commit();

        // single-sync 3-stage pipeline over 24 chunks
        for (int ck = 0; ck < 24; ck++) {
            asm volatile("cp.async.wait_group 1;\n");   // chunk ck arrived
            __syncthreads();                            // readers of (ck-1) done
            if (ck + 2 < 24) {                          // issue chunk ck+2
                int st = (ck + 2) % NSTAGE;             // == (ck-1)%NSTAGE: safe
                cp16(hs_dst + st * 64 * HS_LD, hsrc + (ck + 2) * 32);
            }
            cp_commit();                                // keep group count in lockstep
            const float* Hb = Hs + (ck % NSTAGE) * 64 * HS_LD;
#pragma unroll
            for (int k8 = 0; k8 < 4; k8++) {
                wmma::fragment<wmma::matrix_a, 16, 16, 8, wmma::precision::tf32, wmma::row_major> af;
                wmma::load_matrix_sync(af, Hb + (wm * 16) * HS_LD + k8 * 8, HS_LD);
                wmma::fragment<wmma::matrix_b, 16, 16, 8, wmma::precision::tf32, wmma::row_major> bf;
                wmma::load_matrix_sync(bf, Ws + (ck * 32 + k8 * 8) * WS_LD + wn * 16, WS_LD);
                wmma::mma_sync(acc, af, bf, acc);
            }
        }

        __syncthreads();   // all mma reads done; safe to overlay Gs on Hs
        wmma::store_matrix_sync(Gs + (wm * 16) * GS_LD + wn * 16, acc, GS_LD,
                                wmma::mem_row_major);
        __syncthreads();

        // fused cell update; write h (tf32-rounded) first: it's the critical path
        {
            float gi = Gs[bb0 * GS_LD +  0 + j] + xv00 + bs[j];
            float gj = Gs[bb0 * GS_LD + 16 + j] + xv01 + bs[16 + j];
            float gf = Gs[bb0 * GS_LD + 32 + j] + xv02 + bs[32 + j];
            float go = Gs[bb0 * GS_LD + 48 + j] + xv03 + bs[48 + j];
            float nc = c0 * sigmoidf(gf + 1.f) + sigmoidf(gi) * tanhf(gj);
            float nh = tanhf(nc) * sigmoidf(go);
            if (a0) { c0 = nc; h0 = nh; }

            float gi1 = Gs[bb1 * GS_LD +  0 + j] + xv10 + bs[j];
            float gj1 = Gs[bb1 * GS_LD + 16 + j] + xv11 + bs[16 + j];
            float gf1 = Gs[bb1 * GS_LD + 32 + j] + xv12 + bs[32 + j];
            float go1 = Gs[bb1 * GS_LD + 48 + j] + xv13 + bs[48 + j];
            float nc1 = c1 * sigmoidf(gf1 + 1.f) + sigmoidf(gi1) * tanhf(gj1);
            float nh1 = tanhf(nc1) * sigmoidf(go1);
            if (a1) { c1 = nc1; h1 = nh1; }

            hdst[bb0 * HH + jg] = wmma::__float_to_tf32(h0);
            hdst[bb1 * HH + jg] = wmma::__float_to_tf32(h1);
            __threadfence();   // h visible before barrier arrival

            int to0 = (dir && a0) ? (L0 - 1 - t) : t;
            out[((size_t)bb0 * TT + to0) * (2 * HH) + dir * HH + jg] = a0 ? nh : 0.f;
            int to1 = (dir && a1) ? (L1 - 1 - t) : t;
            out[((size_t)bb1 * TT + to1) * (2 * HH) + dir * HH + jg] = a1 ? nh1 : 0.f;
        }

        grid_sync();
    }

    // final state_h = concat(h_fw, h_bw), appended after outputs
    out[(size_t)BB * TT * 2 * HH + (size_t)bb0 * 2 * HH + dir * HH + jg] = h0;
    out[(size_t)BB * TT * 2 * HH + (size_t)bb1 * 2 * HH + dir * HH + jg] = h1;
}

// ---------------------------------------------------------------------------
extern "C" void kernel_launch(void* const* d_in, const int* in_sizes, int n_in,
                              void* d_out, int out_size)
{
    const float* seq     = (const float*)d_in[0];
    const int*   seq_len = (const int*)d_in[1];
    const float* Wfw     = (const float*)d_in[2];
    const float* bfw     = (const float*)d_in[3];
    const float* Wbw     = (const float*)d_in[4];
    const float* bbw     = (const float*)d_in[5];
    float* out = (float*)d_out;

    const int smem_bytes = (768 * WS_LD + NSTAGE * 64 * HS_LD) * 4;  // 230400
    cudaFuncSetAttribute(lstm_persistent,
                         cudaFuncAttributeMaxDynamicSharedMemorySize, smem_bytes);

    xproj_kernel<<<dim3(MMROWS / 128, NG / 64, 2), 256>>>(seq, Wfw, Wbw);

    lstm_persistent<<<NCTA, 512, smem_bytes>>>(seq_len, Wfw, bfw, Wbw, bbw, out);
}

// round 5
// speedup vs baseline: 1.7050x; 1.7050x over previous
#include <cuda_runtime.h>
#include <mma.h>
#include <cstddef>
#include <cstdint>

using namespace nvcuda;

#define BB 64
#define TT 512
#define DD 512
#define HH 768
#define NG 3072              // 4*H
#define MMROWS (BB * TT)     // 32768
#define NCTA 96              // 2 dirs x 48 column blocks
#define NCTA_DIR 48          // per-direction barrier population
#define WS_LD 68             // Ws row pad (as in R3 baseline)
#define HS_LD 36             // Hs chunk row pad (32 + 4)
#define GS_LD 68

// ---------------- scratch (device globals: the sanctioned scratch path) ----
__device__ float g_xp[(size_t)2 * MMROWS * NG];   // [dir][b*T + t][4H]
__device__ float g_h[2][2][BB * HH];              // [dir][parity][b*H] (tf32-rounded)
__device__ unsigned g_bar_count[2];
__device__ unsigned g_bar_gen[2];

__device__ __forceinline__ float sigmoidf(float x) {
    return 1.0f / (1.0f + expf(-x));
}

// ---------------------------------------------------------------------------
// per-direction software grid barrier (48 CTAs; 1 CTA/SM co-residency)
// tight poll, no nanosleep: wake latency ~ one L2 round trip.
// ---------------------------------------------------------------------------
__device__ __forceinline__ void grid_sync_dir(int dir) {
    __syncthreads();
    if (threadIdx.x == 0) {
        unsigned gen = *((volatile unsigned*)&g_bar_gen[dir]);
        __threadfence();   // h stores visible before arrival
        unsigned arr = atomicAdd(&g_bar_count[dir], 1u);
        if (arr == NCTA_DIR - 1) {
            g_bar_count[dir] = 0;
            __threadfence();
            atomicAdd(&g_bar_gen[dir], 1u);
        } else {
            while (*((volatile unsigned*)&g_bar_gen[dir]) == gen) { }
        }
        __threadfence();   // acquire: others' h stores visible after release
    }
    __syncthreads();
}

// ---------------------------------------------------------------------------
// xproj: xp[dir][m, n] = seq[m, :] @ W_dir[0:D, n]   (unchanged; known-good)
// ---------------------------------------------------------------------------
__global__ void __launch_bounds__(256) xproj_kernel(
    const float* __restrict__ seq,
    const float* __restrict__ Wfw,
    const float* __restrict__ Wbw)
{
    const int dir = blockIdx.z;
    const float* W = dir ? Wbw : Wfw;
    float* xp = g_xp + (size_t)dir * MMROWS * NG;

    const int m0 = blockIdx.x * 128;
    const int n0 = blockIdx.y * 64;

    __shared__ __align__(16) float As[128][20];
    __shared__ __align__(16) float Bs[16][68];

    const int tid = threadIdx.x;
    const int w = tid >> 5;
    const int wm = w & 3;
    const int wn = w >> 2;

    wmma::fragment<wmma::accumulator, 16, 16, 8, float> acc[2][2];
#pragma unroll
    for (int i = 0; i < 2; i++)
#pragma unroll
        for (int j = 0; j < 2; j++)
            wmma::fill_fragment(acc[i][j], 0.0f);

    float ra[8], rb[4];
#pragma unroll
    for (int e = 0; e < 8; e++) {
        int idx = e * 256 + tid; int r = idx >> 4, c = idx & 15;
        ra[e] = seq[(size_t)(m0 + r) * DD + c];
    }
#pragma unroll
    for (int e = 0; e < 4; e++) {
        int idx = e * 256 + tid; int r = idx >> 6, c = idx & 63;
        rb[e] = W[(size_t)r * NG + n0 + c];
    }

    for (int kt = 0; kt < DD / 16; kt++) {
        __syncthreads();
#pragma unroll
        for (int e = 0; e < 8; e++) {
            int idx = e * 256 + tid; int r = idx >> 4, c = idx & 15;
            As[r][c] = ra[e];
        }
#pragma unroll
        for (int e = 0; e < 4; e++) {
            int idx = e * 256 + tid; int r = idx >> 6, c = idx & 63;
            Bs[r][c] = rb[e];
        }
        __syncthreads();

        if (kt + 1 < DD / 16) {
            int k0 = (kt + 1) * 16;
#pragma unroll
            for (int e = 0; e < 8; e++) {
                int idx = e * 256 + tid; int r = idx >> 4, c = idx & 15;
                ra[e] = seq[(size_t)(m0 + r) * DD + k0 + c];
            }
#pragma unroll
            for (int e = 0; e < 4; e++) {
                int idx = e * 256 + tid; int r = idx >> 6, c = idx & 63;
                rb[e] = W[(size_t)(k0 + r) * NG + n0 + c];
            }
        }

#pragma unroll
        for (int k8 = 0; k8 < 16; k8 += 8) {
            wmma::fragment<wmma::matrix_a, 16, 16, 8, wmma::precision::tf32, wmma::row_major> af[2];
            wmma::fragment<wmma::matrix_b, 16, 16, 8, wmma::precision::tf32, wmma::row_major> bf[2];
#pragma unroll
            for (int fm = 0; fm < 2; fm++) {
                wmma::load_matrix_sync(af[fm], &As[wm * 32 + fm * 16][k8], 20);
#pragma unroll
                for (int i = 0; i < af[fm].num_elements; i++)
                    af[fm].x[i] = wmma::__float_to_tf32(af[fm].x[i]);
            }
#pragma unroll
            for (int fn = 0; fn < 2; fn++) {
                wmma::load_matrix_sync(bf[fn], &Bs[k8][wn * 32 + fn * 16], 68);
#pragma unroll
                for (int i = 0; i < bf[fn].num_elements; i++)
                    bf[fn].x[i] = wmma::__float_to_tf32(bf[fn].x[i]);
            }
#pragma unroll
            for (int fm = 0; fm < 2; fm++)
#pragma unroll
                for (int fn = 0; fn < 2; fn++)
                    wmma::mma_sync(acc[fm][fn], af[fm], bf[fn], acc[fm][fn]);
        }
    }

#pragma unroll
    for (int fm = 0; fm < 2; fm++)
#pragma unroll
        for (int fn = 0; fn < 2; fn++) {
            size_t row = m0 + wm * 32 + fm * 16;
            size_t col = n0 + wn * 32 + fn * 16;
            wmma::store_matrix_sync(xp + row * NG + col, acc[fm][fn], NG,
                                    wmma::mem_row_major);
        }
}

// ---------------------------------------------------------------------------
// cp.async 16B helper (R3 baseline: .ca)
// ---------------------------------------------------------------------------
__device__ __forceinline__ void cp16(float* smem_dst, const float* gmem_src) {
    unsigned d = (unsigned)__cvta_generic_to_shared(smem_dst);
    asm volatile("cp.async.ca.shared.global [%0], [%1], 16;\n"
                 :: "r"(d), "l"(gmem_src));
}

// ---------------------------------------------------------------------------
// Persistent recurrence kernel (R3 mainloop structure, exactly).
// Changes vs R3: h stored pre-rounded to tf32 (no A-frag F2FP in loop);
// per-direction barriers with tight polling.
// ---------------------------------------------------------------------------
__global__ void __launch_bounds__(512, 1) lstm_persistent(
    const int* __restrict__ seq_len,
    const float* __restrict__ Wfw, const float* __restrict__ bfw,
    const float* __restrict__ Wbw, const float* __restrict__ bbw,
    float* __restrict__ out)
{
    const int dir = blockIdx.x / 48;
    const int jb  = blockIdx.x % 48;
    const float* W    = dir ? Wbw : Wfw;
    const float* bias = dir ? bbw : bfw;
    const float* xp = g_xp + (size_t)dir * MMROWS * NG;

    extern __shared__ float smem[];
    float* Ws = smem;                       // [768][WS_LD]
    float* Hs = smem + 768 * WS_LD;         // [2][64][HS_LD]
    float* Gs = Hs;                         // [64][GS_LD] overlay (post-mainloop)
    __shared__ float bs[64];

    const int tid = threadIdx.x;
    const int w  = tid >> 5;
    const int wm = w & 3;      // 16-row (batch) block
    const int wn = w >> 2;     // 16-col (gate) block

    // --- one-time: load + tf32-round recurrent weight slice ---
    for (int i = tid; i < 768 * 64; i += 512) {
        int k = i >> 6, n = i & 63;
        int g = n >> 4, c = n & 15;
        float v = W[(size_t)(DD + k) * NG + g * HH + jb * 16 + c];
        Ws[k * WS_LD + n] = wmma::__float_to_tf32(v);
    }
    if (tid < 64) {
        int g = tid >> 4, c = tid & 15;
        bs[tid] = bias[g * HH + jb * 16 + c];
    }

    // --- per-thread cell ownership: (b, j) fixed for the whole run ---
    const int j  = tid & 15;
    const int jg = jb * 16 + j;
    const int bb0 = tid >> 4;       // 0..31
    const int bb1 = bb0 + 32;       // 32..63
    const int L0 = seq_len[bb0];
    const int L1 = seq_len[bb1];
    float c0 = 0.f, c1 = 0.f, h0 = 0.f, h1 = 0.f;

    g_h[dir][0][bb0 * HH + jg] = 0.f;
    g_h[dir][0][bb1 * HH + jg] = 0.f;

    // chunk-copy thread mapping: 64 rows x 32 cols = 512 x (1 float4)
    const int cr = tid >> 3;
    const int cc = (tid & 7) * 4;

    grid_sync_dir(dir);

    for (int t = 0; t < TT; t++) {
        const int parr = t & 1;
        const float* hsrc = g_h[dir][parr];
        float* hdst = g_h[dir][parr ^ 1];

        // xp operand prefetch (in flight across the mainloop)
        const bool a0 = t < L0, a1 = t < L1;
        const int tx0 = dir ? (a0 ? L0 - 1 - t : t) : t;
        const int tx1 = dir ? (a1 ? L1 - 1 - t : t) : t;
        const float* x0 = xp + ((size_t)bb0 * TT + tx0) * NG + jg;
        const float* x1 = xp + ((size_t)bb1 * TT + tx1) * NG + jg;
        float xv00 = x0[0], xv01 = x0[HH], xv02 = x0[2 * HH], xv03 = x0[3 * HH];
        float xv10 = x1[0], xv11 = x1[HH], xv12 = x1[2 * HH], xv13 = x1[3 * HH];

        wmma::fragment<wmma::accumulator, 16, 16, 8, float> acc;
        wmma::fill_fragment(acc, 0.f);

        // prologue: issue chunks 0, 1
        cp16(Hs + 0 * 64 * HS_LD + cr * HS_LD + cc, hsrc + cr * HH + 0 + cc);
        asm volatile("cp.async.commit_group;\n");
        cp16(Hs + 1 * 64 * HS_LD + cr * HS_LD + cc, hsrc + cr * HH + 32 + cc);
        asm volatile("cp.async.commit_group;\n");

        for (int ck = 0; ck < 24; ck++) {
            if (ck < 23) asm volatile("cp.async.wait_group 1;\n");
            else         asm volatile("cp.async.wait_group 0;\n");
            __syncthreads();
            float* Hb = Hs + (ck & 1) * 64 * HS_LD;
#pragma unroll
            for (int k8 = 0; k8 < 4; k8++) {
                wmma::fragment<wmma::matrix_a, 16, 16, 8, wmma::precision::tf32, wmma::row_major> af;
                wmma::load_matrix_sync(af, Hb + (wm * 16) * HS_LD + k8 * 8, HS_LD);
                // h is pre-rounded tf32 in g_h: no conversion needed
                wmma::fragment<wmma::matrix_b, 16, 16, 8, wmma::precision::tf32, wmma::row_major> bf;
                wmma::load_matrix_sync(bf, Ws + (ck * 32 + k8 * 8) * WS_LD + wn * 16, WS_LD);
                wmma::mma_sync(acc, af, bf, acc);
            }
            __syncthreads();
            if (ck + 2 < 24) {
                cp16(Hs + (ck & 1) * 64 * HS_LD + cr * HS_LD + cc,
                     hsrc + cr * HH + (ck + 2) * 32 + cc);
                asm volatile("cp.async.commit_group;\n");
            }
        }

        // stage gates into smem (overlays Hs; all mma done + synced)
        wmma::store_matrix_sync(Gs + (wm * 16) * GS_LD + wn * 16, acc, GS_LD,
                                wmma::mem_row_major);
        __syncthreads();

        // fused cell update (registers carry c and h); h stored tf32-rounded
        {
            float gi = Gs[bb0 * GS_LD +  0 + j] + xv00 + bs[j];
            float gj = Gs[bb0 * GS_LD + 16 + j] + xv01 + bs[16 + j];
            float gf = Gs[bb0 * GS_LD + 32 + j] + xv02 + bs[32 + j];
            float go = Gs[bb0 * GS_LD + 48 + j] + xv03 + bs[48 + j];
            float nc = c0 * sigmoidf(gf + 1.f) + sigmoidf(gi) * tanhf(gj);
            float nh = tanhf(nc) * sigmoidf(go);
            if (a0) { c0 = nc; h0 = nh; }
            hdst[bb0 * HH + jg] = wmma::__float_to_tf32(h0);
            int to = (dir && a0) ? (L0 - 1 - t) : t;
            out[((size_t)bb0 * TT + to) * (2 * HH) + dir * HH + jg] = a0 ? nh : 0.f;
        }
        {
            float gi = Gs[bb1 * GS_LD +  0 + j] + xv10 + bs[j];
            float gj = Gs[bb1 * GS_LD + 16 + j] + xv11 + bs[16 + j];
            float gf = Gs[bb1 * GS_LD + 32 + j] + xv12 + bs[32 + j];
            float go = Gs[bb1 * GS_LD + 48 + j] + xv13 + bs[48 + j];
            float nc = c1 * sigmoidf(gf + 1.f) + sigmoidf(gi) * tanhf(gj);
            float nh = tanhf(nc) * sigmoidf(go);
            if (a1) { c1 = nc; h1 = nh; }
            hdst[bb1 * HH + jg] = wmma::__float_to_tf32(h1);
            int to = (dir && a1) ? (L1 - 1 - t) : t;
            out[((size_t)bb1 * TT + to) * (2 * HH) + dir * HH + jg] = a1 ? nh : 0.f;
        }

        grid_sync_dir(dir);   // includes release fence for h stores
    }

    // final state_h = concat(h_fw, h_bw), appended after outputs
    out[(size_t)BB * TT * 2 * HH + (size_t)bb0 * 2 * HH + dir * HH + jg] = h0;
    out[(size_t)BB * TT * 2 * HH + (size_t)bb1 * 2 * HH + dir * HH + jg] = h1;
}

// ---------------------------------------------------------------------------
extern "C" void kernel_launch(void* const* d_in, const int* in_sizes, int n_in,
                              void* d_out, int out_size)
{
    const float* seq     = (const float*)d_in[0];
    const int*   seq_len = (const int*)d_in[1];
    const float* Wfw     = (const float*)d_in[2];
    const float* bfw     = (const float*)d_in[3];
    const float* Wbw     = (const float*)d_in[4];
    const float* bbw     = (const float*)d_in[5];
    float* out = (float*)d_out;

    const int smem_bytes = (768 * WS_LD + 2 * 64 * HS_LD) * 4;  // 227328
    cudaFuncSetAttribute(lstm_persistent,
                         cudaFuncAttributeMaxDynamicSharedMemorySize, smem_bytes);

    xproj_kernel<<<dim3(MMROWS / 128, NG / 64, 2), 256>>>(seq, Wfw, Wbw);

    lstm_persistent<<<NCTA, 512, smem_bytes>>>(seq_len, Wfw, bfw, Wbw, bbw, out);
}

// round 7
// speedup vs baseline: 1.7068x; 1.0011x over previous
#include <cuda_runtime.h>
#include <mma.h>
#include <cstddef>
#include <cstdint>

using namespace nvcuda;

#define BB 64
#define TT 512
#define DD 512
#define HH 768
#define NG 3072              // 4*H
#define MMROWS (BB * TT)     // 32768
#define NCTA 96              // 2 dirs x 48 column blocks
#define NCTA_DIR 48          // per-direction barrier population
#define WS_LD 68             // Ws row pad (R3/R5 baseline)
#define HS_LD 36             // Hs chunk row pad (32 + 4)
#define GS_LD 68

// ---------------- scratch (device globals: the sanctioned scratch path) ----
__device__ float g_xp[(size_t)2 * MMROWS * NG];   // [dir][b*T + t][4H]
__device__ float g_h[2][2][BB * HH];              // [dir][parity][b*H] (tf32-rounded)
__device__ unsigned g_bar_count[2];
__device__ unsigned g_bar_gen[2];

__device__ __forceinline__ float sigmoidf(float x) {
    return 1.0f / (1.0f + __expf(-x));
}

// ---------------------------------------------------------------------------
// split per-direction grid barrier: arrive (release fence covers ONLY stores
// issued before it) ... caller work ... wait.
// Wait polls tight for fast wake, then yields via nanosleep (watchdog-safe).
// ---------------------------------------------------------------------------
__device__ __forceinline__ unsigned bar_arrive(int dir) {
    // call AFTER __syncthreads(); thread 0 only
    unsigned gen = *((volatile unsigned*)&g_bar_gen[dir]);
    __threadfence();                       // release: h stores visible
    unsigned arr = atomicAdd(&g_bar_count[dir], 1u);
    if (arr == NCTA_DIR - 1) {
        g_bar_count[dir] = 0;
        __threadfence();
        atomicAdd(&g_bar_gen[dir], 1u);
    }
    return gen;
}
__device__ __forceinline__ void bar_wait(int dir, unsigned gen) {
    // thread 0 only
    int spins = 0;
    while (*((volatile unsigned*)&g_bar_gen[dir]) == gen) {
        if (++spins > 64) __nanosleep(20);
    }
    __threadfence();                       // acquire
}

// ---------------------------------------------------------------------------
// xproj: xp[dir][m, n] = seq[m, :] @ W_dir[0:D, n]   (unchanged; known-good)
// ---------------------------------------------------------------------------
__global__ void __launch_bounds__(256) xproj_kernel(
    const float* __restrict__ seq,
    const float* __restrict__ Wfw,
    const float* __restrict__ Wbw)
{
    const int dir = blockIdx.z;
    const float* W = dir ? Wbw : Wfw;
    float* xp = g_xp + (size_t)dir * MMROWS * NG;

    const int m0 = blockIdx.x * 128;
    const int n0 = blockIdx.y * 64;

    __shared__ __align__(16) float As[128][20];
    __shared__ __align__(16) float Bs[16][68];

    const int tid = threadIdx.x;
    const int w = tid >> 5;
    const int wm = w & 3;
    const int wn = w >> 2;

    wmma::fragment<wmma::accumulator, 16, 16, 8, float> acc[2][2];
#pragma unroll
    for (int i = 0; i < 2; i++)
#pragma unroll
        for (int j = 0; j < 2; j++)
            wmma::fill_fragment(acc[i][j], 0.0f);

    float ra[8], rb[4];
#pragma unroll
    for (int e = 0; e < 8; e++) {
        int idx = e * 256 + tid; int r = idx >> 4, c = idx & 15;
        ra[e] = seq[(size_t)(m0 + r) * DD + c];
    }
#pragma unroll
    for (int e = 0; e < 4; e++) {
        int idx = e * 256 + tid; int r = idx >> 6, c = idx & 63;
        rb[e] = W[(size_t)r * NG + n0 + c];
    }

    for (int kt = 0; kt < DD / 16; kt++) {
        __syncthreads();
#pragma unroll
        for (int e = 0; e < 8; e++) {
            int idx = e * 256 + tid; int r = idx >> 4, c = idx & 15;
            As[r][c] = ra[e];
        }
#pragma unroll
        for (int e = 0; e < 4; e++) {
            int idx = e * 256 + tid; int r = idx >> 6, c = idx & 63;
            Bs[r][c] = rb[e];
        }
        __syncthreads();

        if (kt + 1 < DD / 16) {
            int k0 = (kt + 1) * 16;
#pragma unroll
            for (int e = 0; e < 8; e++) {
                int idx = e * 256 + tid; int r = idx >> 4, c = idx & 15;
                ra[e] = seq[(size_t)(m0 + r) * DD + k0 + c];
            }
#pragma unroll
            for (int e = 0; e < 4; e++) {
                int idx = e * 256 + tid; int r = idx >> 6, c = idx & 63;
                rb[e] = W[(size_t)(k0 + r) * NG + n0 + c];
            }
        }

#pragma unroll
        for (int k8 = 0; k8 < 16; k8 += 8) {
            wmma::fragment<wmma::matrix_a, 16, 16, 8, wmma::precision::tf32, wmma::row_major> af[2];
            wmma::fragment<wmma::matrix_b, 16, 16, 8, wmma::precision::tf32, wmma::row_major> bf[2];
#pragma unroll
            for (int fm = 0; fm < 2; fm++) {
                wmma::load_matrix_sync(af[fm], &As[wm * 32 + fm * 16][k8], 20);
#pragma unroll
                for (int i = 0; i < af[fm].num_elements; i++)
                    af[fm].x[i] = wmma::__float_to_tf32(af[fm].x[i]);
            }
#pragma unroll
            for (int fn = 0; fn < 2; fn++) {
                wmma::load_matrix_sync(bf[fn], &Bs[k8][wn * 32 + fn * 16], 68);
#pragma unroll
                for (int i = 0; i < bf[fn].num_elements; i++)
                    bf[fn].x[i] = wmma::__float_to_tf32(bf[fn].x[i]);
            }
#pragma unroll
            for (int fm = 0; fm < 2; fm++)
#pragma unroll
                for (int fn = 0; fn < 2; fn++)
                    wmma::mma_sync(acc[fm][fn], af[fm], bf[fn], acc[fm][fn]);
        }
    }

#pragma unroll
    for (int fm = 0; fm < 2; fm++)
#pragma unroll
        for (int fn = 0; fn < 2; fn++) {
            size_t row = m0 + wm * 32 + fm * 16;
            size_t col = n0 + wn * 32 + fn * 16;
            wmma::store_matrix_sync(xp + row * NG + col, acc[fm][fn], NG,
                                    wmma::mem_row_major);
        }
}

// ---------------------------------------------------------------------------
// cp.async 16B helper
// ---------------------------------------------------------------------------
__device__ __forceinline__ void cp16(float* smem_dst, const float* gmem_src) {
    unsigned d = (unsigned)__cvta_generic_to_shared(smem_dst);
    asm volatile("cp.async.ca.shared.global [%0], [%1], 16;\n"
                 :: "r"(d), "l"(gmem_src));
}

// ---------------------------------------------------------------------------
// Persistent recurrence kernel (R5 mainloop, exactly).
// Change vs R5: barrier split arrive -> out-stores -> wait, so the release
// fence drains only the small L2-bound h stores; DRAM out-stores drain in
// the straggler-wait shadow.
// ---------------------------------------------------------------------------
__global__ void __launch_bounds__(512, 1) lstm_persistent(
    const int* __restrict__ seq_len,
    const float* __restrict__ Wfw, const float* __restrict__ bfw,
    const float* __restrict__ Wbw, const float* __restrict__ bbw,
    float* __restrict__ out)
{
    const int dir = blockIdx.x / 48;
    const int jb  = blockIdx.x % 48;
    const float* W    = dir ? Wbw : Wfw;
    const float* bias = dir ? bbw : bfw;
    const float* xp = g_xp + (size_t)dir * MMROWS * NG;

    extern __shared__ float smem[];
    float* Ws = smem;                       // [768][WS_LD]
    float* Hs = smem + 768 * WS_LD;         // [2][64][HS_LD]
    float* Gs = Hs;                         // [64][GS_LD] overlay (post-mainloop)
    __shared__ float bs[64];
    __shared__ unsigned s_gen;

    const int tid = threadIdx.x;
    const int w  = tid >> 5;
    const int wm = w & 3;      // 16-row (batch) block
    const int wn = w >> 2;     // 16-col (gate) block

    // --- one-time: load + tf32-round recurrent weight slice ---
    for (int i = tid; i < 768 * 64; i += 512) {
        int k = i >> 6, n = i & 63;
        int g = n >> 4, c = n & 15;
        float v = W[(size_t)(DD + k) * NG + g * HH + jb * 16 + c];
        Ws[k * WS_LD + n] = wmma::__float_to_tf32(v);
    }
    if (tid < 64) {
        int g = tid >> 4, c = tid & 15;
        bs[tid] = bias[g * HH + jb * 16 + c];
    }

    // --- per-thread cell ownership: (b, j) fixed for the whole run ---
    const int j  = tid & 15;
    const int jg = jb * 16 + j;
    const int bb0 = tid >> 4;       // 0..31
    const int bb1 = bb0 + 32;       // 32..63
    const int L0 = seq_len[bb0];
    const int L1 = seq_len[bb1];
    float c0 = 0.f, c1 = 0.f, h0 = 0.f, h1 = 0.f;

    g_h[dir][0][bb0 * HH + jg] = 0.f;
    g_h[dir][0][bb1 * HH + jg] = 0.f;

    // chunk-copy thread mapping: 64 rows x 32 cols = 512 x (1 float4)
    const int cr = tid >> 3;
    const int cc = (tid & 7) * 4;

    // initial full barrier
    __syncthreads();
    if (tid == 0) { unsigned g0 = bar_arrive(dir); bar_wait(dir, g0); }
    __syncthreads();

    for (int t = 0; t < TT; t++) {
        const int parr = t & 1;
        const float* hsrc = g_h[dir][parr];
        float* hdst = g_h[dir][parr ^ 1];

        // xp operand prefetch (in flight across the mainloop)
        const bool a0 = t < L0, a1 = t < L1;
        const int tx0 = dir ? (a0 ? L0 - 1 - t : t) : t;
        const int tx1 = dir ? (a1 ? L1 - 1 - t : t) : t;
        const float* x0 = xp + ((size_t)bb0 * TT + tx0) * NG + jg;
        const float* x1 = xp + ((size_t)bb1 * TT + tx1) * NG + jg;
        float xv00 = x0[0], xv01 = x0[HH], xv02 = x0[2 * HH], xv03 = x0[3 * HH];
        float xv10 = x1[0], xv11 = x1[HH], xv12 = x1[2 * HH], xv13 = x1[3 * HH];

        wmma::fragment<wmma::accumulator, 16, 16, 8, float> acc;
        wmma::fill_fragment(acc, 0.f);

        // prologue: issue chunks 0, 1
        cp16(Hs + 0 * 64 * HS_LD + cr * HS_LD + cc, hsrc + cr * HH + 0 + cc);
        asm volatile("cp.async.commit_group;\n");
        cp16(Hs + 1 * 64 * HS_LD + cr * HS_LD + cc, hsrc + cr * HH + 32 + cc);
        asm volatile("cp.async.commit_group;\n");

        for (int ck = 0; ck < 24; ck++) {
            if (ck < 23) asm volatile("cp.async.wait_group 1;\n");
            else         asm volatile("cp.async.wait_group 0;\n");
            __syncthreads();
            float* Hb = Hs + (ck & 1) * 64 * HS_LD;
#pragma unroll
            for (int k8 = 0; k8 < 4; k8++) {
                wmma::fragment<wmma::matrix_a, 16, 16, 8, wmma::precision::tf32, wmma::row_major> af;
                wmma::load_matrix_sync(af, Hb + (wm * 16) * HS_LD + k8 * 8, HS_LD);
                // h is pre-rounded tf32 in g_h: no conversion needed
                wmma::fragment<wmma::matrix_b, 16, 16, 8, wmma::precision::tf32, wmma::row_major> bf;
                wmma::load_matrix_sync(bf, Ws + (ck * 32 + k8 * 8) * WS_LD + wn * 16, WS_LD);
                wmma::mma_sync(acc, af, bf, acc);
            }
            __syncthreads();
            if (ck + 2 < 24) {
                cp16(Hs + (ck & 1) * 64 * HS_LD + cr * HS_LD + cc,
                     hsrc + cr * HH + (ck + 2) * 32 + cc);
                asm volatile("cp.async.commit_group;\n");
            }
        }

        // stage gates into smem (overlays Hs; all mma done + synced)
        wmma::store_matrix_sync(Gs + (wm * 16) * GS_LD + wn * 16, acc, GS_LD,
                                wmma::mem_row_major);
        __syncthreads();

        // fused cell update; h stores (L2, small) BEFORE the arrive fence
        float nh0, nh1;
        {
            float gi = Gs[bb0 * GS_LD +  0 + j] + xv00 + bs[j];
            float gj = Gs[bb0 * GS_LD + 16 + j] + xv01 + bs[16 + j];
            float gf = Gs[bb0 * GS_LD + 32 + j] + xv02 + bs[32 + j];
            float go = Gs[bb0 * GS_LD + 48 + j] + xv03 + bs[48 + j];
            float nc = c0 * sigmoidf(gf + 1.f) + sigmoidf(gi) * tanhf(gj);
            nh0 = tanhf(nc) * sigmoidf(go);
            if (a0) { c0 = nc; h0 = nh0; }
            hdst[bb0 * HH + jg] = wmma::__float_to_tf32(h0);
        }
        {
            float gi = Gs[bb1 * GS_LD +  0 + j] + xv10 + bs[j];
            float gj = Gs[bb1 * GS_LD + 16 + j] + xv11 + bs[16 + j];
            float gf = Gs[bb1 * GS_LD + 32 + j] + xv12 + bs[32 + j];
            float go = Gs[bb1 * GS_LD + 48 + j] + xv13 + bs[48 + j];
            float nc = c1 * sigmoidf(gf + 1.f) + sigmoidf(gi) * tanhf(gj);
            nh1 = tanhf(nc) * sigmoidf(go);
            if (a1) { c1 = nc; h1 = nh1; }
            hdst[bb1 * HH + jg] = wmma::__float_to_tf32(h1);
        }

        // arrive: fence covers only h stores (out-stores not yet issued)
        __syncthreads();
        if (tid == 0) s_gen = bar_arrive(dir);

        // out-stores (DRAM) drain during the straggler wait
        {
            int to0 = (dir && a0) ? (L0 - 1 - t) : t;
            out[((size_t)bb0 * TT + to0) * (2 * HH) + dir * HH + jg] = a0 ? nh0 : 0.f;
            int to1 = (dir && a1) ? (L1 - 1 - t) : t;
            out[((size_t)bb1 * TT + to1) * (2 * HH) + dir * HH + jg] = a1 ? nh1 : 0.f;
        }

        if (tid == 0) bar_wait(dir, s_gen);
        __syncthreads();
    }

    // final state_h = concat(h_fw, h_bw), appended after outputs
    out[(size_t)BB * TT * 2 * HH + (size_t)bb0 * 2 * HH + dir * HH + jg] = h0;
    out[(size_t)BB * TT * 2 * HH + (size_t)bb1 * 2 * HH + dir * HH + jg] = h1;
}

// ---------------------------------------------------------------------------
extern "C" void kernel_launch(void* const* d_in, const int* in_sizes, int n_in,
                              void* d_out, int out_size)
{
    const float* seq     = (const float*)d_in[0];
    const int*   seq_len = (const int*)d_in[1];
    const float* Wfw     = (const float*)d_in[2];
    const float* bfw     = (const float*)d_in[3];
    const float* Wbw     = (const float*)d_in[4];
    const float* bbw     = (const float*)d_in[5];
    float* out = (float*)d_out;

    const int smem_bytes = (768 * WS_LD + 2 * 64 * HS_LD) * 4;  // 227328
    cudaFuncSetAttribute(lstm_persistent,
                         cudaFuncAttributeMaxDynamicSharedMemorySize, smem_bytes);

    xproj_kernel<<<dim3(MMROWS / 128, NG / 64, 2), 256>>>(seq, Wfw, Wbw);

    lstm_persistent<<<NCTA, 512, smem_bytes>>>(seq_len, Wfw, bfw, Wbw, bbw, out);
}